// round 5
// baseline (speedup 1.0000x reference)
#include <cuda_runtime.h>
#include <math.h>

// Scratch (no cudaMalloc allowed)
__device__ float g_feats[32 * 1280];   // [B, (K+1)*C] pooled means
__device__ float g_w1[32 * 256];       // [B, C] sigmoid self-gate
__device__ float g_w2[32 * 4 * 256];   // [B, K, C] softmax branch gates

#define B_ 32
#define C_ 256
#define K_ 4
#define HW_ 1024
#define MID_ 32
#define FEAT_ 1280   // (K+1)*C

// ---------------- Kernel 1: global average pool (lean) ----------------
// One warp per (b, slot, c) row of 1024 contiguous floats. 40960 warps total.
__global__ void k_means(const float* __restrict__ y,
                        const float* __restrict__ x0,
                        const float* __restrict__ x1,
                        const float* __restrict__ x2,
                        const float* __restrict__ x3) {
    int warp = (blockIdx.x * blockDim.x + threadIdx.x) >> 5;
    int lane = threadIdx.x & 31;
    int b = warp / FEAT_;
    int j = warp - b * FEAT_;       // slot*256 + c
    int slot = j >> 8;
    int c = j & 255;
    const float* base;
    switch (slot) {
        case 0: base = y;  break;
        case 1: base = x0; break;
        case 2: base = x1; break;
        case 3: base = x2; break;
        default: base = x3; break;
    }
    const float4* p = reinterpret_cast<const float4*>(base + (size_t)(b * C_ + c) * HW_);
    float s = 0.f;
#pragma unroll
    for (int i = 0; i < 8; i++) {        // 8 * 32 lanes * 4 floats = 1024
        float4 v = p[lane + i * 32];
        s += (v.x + v.y) + (v.z + v.w);
    }
#pragma unroll
    for (int o = 16; o; o >>= 1) s += __shfl_xor_sync(0xffffffffu, s, o);
    if (lane == 0) g_feats[warp] = s * (1.0f / 1024.0f);
}

// ---------------- Kernel 2: gate MLP ----------------
// PDL secondary (waits on k_means data) AND PDL primary for k_apply:
// triggers at entry so apply's grid launches and prefetches concurrently.
__global__ void k_gate(const float* __restrict__ conv1_w,   // [32,1280]
                       const float* __restrict__ bn_gamma,
                       const float* __restrict__ bn_beta,
                       const float* __restrict__ bn_mean,
                       const float* __restrict__ bn_var,
                       const float* __restrict__ conv2_w,   // [1280,32]
                       const float* __restrict__ conv2_b) { // [1280]
    // Let dependent k_apply launch right away (it self-synchronizes).
    cudaTriggerProgrammaticLaunchCompletion();

    __shared__ float sf[FEAT_];
    __shared__ float sh[MID_];
    int b = blockIdx.x;
    int t = threadIdx.x;

    // Wait until k_means' writes to g_feats are visible.
    cudaGridDependencySynchronize();

    for (int i = t; i < FEAT_; i += 256) sf[i] = g_feats[b * FEAT_ + i];
    __syncthreads();

    int warp = t >> 5, lane = t & 31;
    // GEMM1: each warp computes 4 of the 32 mid channels
#pragma unroll
    for (int mi = 0; mi < 4; mi++) {
        int mid = warp * 4 + mi;
        const float* wr = conv1_w + mid * FEAT_;
        float s = 0.f;
#pragma unroll
        for (int j0 = 0; j0 < FEAT_; j0 += 32) s = fmaf(sf[j0 + lane], wr[j0 + lane], s);
#pragma unroll
        for (int o = 16; o; o >>= 1) s += __shfl_xor_sync(0xffffffffu, s, o);
        if (lane == 0) {
            float hv = (s - bn_mean[mid]) * (bn_gamma[mid] * rsqrtf(bn_var[mid] + 1e-5f))
                       + bn_beta[mid];
            sh[mid] = fmaxf(hv, 0.f);
        }
    }
    __syncthreads();

    // GEMM2: thread t owns channel c=t across all 5 slots (j = m*256 + t)
    float v[5];
#pragma unroll
    for (int m = 0; m < 5; m++) {
        int j = m * 256 + t;
        float s = conv2_b[j];
        const float* wr = conv2_w + j * MID_;
#pragma unroll
        for (int mid = 0; mid < MID_; mid++) s = fmaf(sh[mid], wr[mid], s);
        v[m] = s;
    }
    g_w1[b * C_ + t] = 1.0f / (1.0f + expf(-v[0]));
    float mx = fmaxf(fmaxf(v[1], v[2]), fmaxf(v[3], v[4]));
    float e1 = expf(v[1] - mx), e2 = expf(v[2] - mx);
    float e3 = expf(v[3] - mx), e4 = expf(v[4] - mx);
    float inv = 1.0f / (e1 + e2 + e3 + e4);
    int gb = b * K_ * C_ + t;
    g_w2[gb + 0 * C_] = e1 * inv;
    g_w2[gb + 1 * C_] = e2 * inv;
    g_w2[gb + 2 * C_] = e3 * inv;
    g_w2[gb + 3 * C_] = e4 * inv;
}

// ---------------- Kernel 3: apply gates (2 sweeps/thread, reversed, PDL) ----------------
// Launches while k_gate runs; issues its 10 gate-independent LDG.128 first,
// then waits on the grid dependency, then reads gates and computes.
__global__ void k_apply(const float* __restrict__ y,
                        const float* __restrict__ x0,
                        const float* __restrict__ x1,
                        const float* __restrict__ x2,
                        const float* __restrict__ x3,
                        float* __restrict__ out) {
    int blk = gridDim.x - 1 - blockIdx.x;            // reversed
    int t = threadIdx.x;
    int i0 = blk * 512 + t;                          // sweep 0 float4 index
    int i1 = i0 + 256;                               // sweep 1

    const float4* Y  = reinterpret_cast<const float4*>(y);
    const float4* X0 = reinterpret_cast<const float4*>(x0);
    const float4* X1 = reinterpret_cast<const float4*>(x1);
    const float4* X2 = reinterpret_cast<const float4*>(x2);
    const float4* X3 = reinterpret_cast<const float4*>(x3);

    // Gate-independent loads first: these overlap with k_gate's execution.
    float4 ya = Y[i0],  yb = Y[i1];
    float4 p0 = X0[i0], q0 = X0[i1];
    float4 p1 = X1[i0], q1 = X1[i1];
    float4 p2 = X2[i0], q2 = X2[i1];
    float4 p3 = X3[i0], q3 = X3[i1];

    // Now wait for k_gate's output to be visible.
    cudaGridDependencySynchronize();

    int bc0 = blk * 2;
    int bc1 = bc0 + 1;
    int b = bc0 >> 8;
    int c0 = bc0 & 255, c1 = bc1 & 255;
    float w1a = g_w1[bc0],               w1b = g_w1[bc1];
    int ga = b * K_ * C_ + c0,           gb = b * K_ * C_ + c1;
    float a0 = g_w2[ga + 0 * C_], b0 = g_w2[gb + 0 * C_];
    float a1 = g_w2[ga + 1 * C_], b1 = g_w2[gb + 1 * C_];
    float a2 = g_w2[ga + 2 * C_], b2 = g_w2[gb + 2 * C_];
    float a3 = g_w2[ga + 3 * C_], b3 = g_w2[gb + 3 * C_];

    float4 r;
    r.x = fmaf(ya.x, w1a, fmaf(a0, p0.x, fmaf(a1, p1.x, fmaf(a2, p2.x, a3 * p3.x))));
    r.y = fmaf(ya.y, w1a, fmaf(a0, p0.y, fmaf(a1, p1.y, fmaf(a2, p2.y, a3 * p3.y))));
    r.z = fmaf(ya.z, w1a, fmaf(a0, p0.z, fmaf(a1, p1.z, fmaf(a2, p2.z, a3 * p3.z))));
    r.w = fmaf(ya.w, w1a, fmaf(a0, p0.w, fmaf(a1, p1.w, fmaf(a2, p2.w, a3 * p3.w))));
    __stcs(reinterpret_cast<float4*>(out) + i0, r);

    float4 s;
    s.x = fmaf(yb.x, w1b, fmaf(b0, q0.x, fmaf(b1, q1.x, fmaf(b2, q2.x, b3 * q3.x))));
    s.y = fmaf(yb.y, w1b, fmaf(b0, q0.y, fmaf(b1, q1.y, fmaf(b2, q2.y, b3 * q3.y))));
    s.z = fmaf(yb.z, w1b, fmaf(b0, q0.z, fmaf(b1, q1.z, fmaf(b2, q2.z, b3 * q3.z))));
    s.w = fmaf(yb.w, w1b, fmaf(b0, q0.w, fmaf(b1, q1.w, fmaf(b2, q2.w, b3 * q3.w))));
    __stcs(reinterpret_cast<float4*>(out) + i1, s);
}

extern "C" void kernel_launch(void* const* d_in, const int* in_sizes, int n_in,
                              void* d_out, int out_size) {
    const float* y       = (const float*)d_in[0];
    const float* x0      = (const float*)d_in[1];
    const float* x1      = (const float*)d_in[2];
    const float* x2      = (const float*)d_in[3];
    const float* x3      = (const float*)d_in[4];
    const float* conv1_w = (const float*)d_in[5];
    const float* bn_g    = (const float*)d_in[6];
    const float* bn_b    = (const float*)d_in[7];
    const float* bn_m    = (const float*)d_in[8];
    const float* bn_v    = (const float*)d_in[9];
    const float* conv2_w = (const float*)d_in[10];
    const float* conv2_b = (const float*)d_in[11];
    float* out = (float*)d_out;

    // Kernel 1: plain launch
    k_means<<<5120, 256>>>(y, x0, x1, x2, x3);

    // PDL attribute: secondary launch may begin while predecessor drains.
    cudaLaunchAttribute attr[1];
    attr[0].id = cudaLaunchAttributeProgrammaticStreamSerialization;
    attr[0].val.programmaticStreamSerializationAllowed = 1;

    {   // Kernel 2: gate MLP, PDL-dependent on k_means
        cudaLaunchConfig_t cfg = {};
        cfg.gridDim = dim3(32, 1, 1);
        cfg.blockDim = dim3(256, 1, 1);
        cfg.dynamicSmemBytes = 0;
        cfg.stream = 0;
        cfg.attrs = attr;
        cfg.numAttrs = 1;
        cudaLaunchKernelEx(&cfg, k_gate, conv1_w, bn_g, bn_b, bn_m, bn_v,
                           conv2_w, conv2_b);
    }
    {   // Kernel 3: apply, PDL-dependent on k_gate (which triggers at entry)
        cudaLaunchConfig_t cfg = {};
        cfg.gridDim = dim3(4096, 1, 1);
        cfg.blockDim = dim3(256, 1, 1);
        cfg.dynamicSmemBytes = 0;
        cfg.stream = 0;
        cfg.attrs = attr;
        cfg.numAttrs = 1;
        cudaLaunchKernelEx(&cfg, k_apply, y, x0, x1, x2, x3, out);
    }
}

// round 6
// speedup vs baseline: 1.0080x; 1.0080x over previous
#include <cuda_runtime.h>
#include <math.h>

// Scratch (no cudaMalloc allowed)
__device__ float g_feats[32 * 1280];   // [B, (K+1)*C] pooled means
__device__ float g_w1[32 * 256];       // [B, C] sigmoid self-gate
__device__ float g_w2[32 * 4 * 256];   // [B, K, C] softmax branch gates

#define B_ 32
#define C_ 256
#define K_ 4
#define HW_ 1024
#define MID_ 32
#define FEAT_ 1280   // (K+1)*C

// ---------------- Kernel 1: global average pool (lean) ----------------
// One warp per (b, slot, c) row of 1024 contiguous floats. 40960 warps total.
__global__ void k_means(const float* __restrict__ y,
                        const float* __restrict__ x0,
                        const float* __restrict__ x1,
                        const float* __restrict__ x2,
                        const float* __restrict__ x3) {
    int warp = (blockIdx.x * blockDim.x + threadIdx.x) >> 5;
    int lane = threadIdx.x & 31;
    int b = warp / FEAT_;
    int j = warp - b * FEAT_;       // slot*256 + c
    int slot = j >> 8;
    int c = j & 255;
    const float* base;
    switch (slot) {
        case 0: base = y;  break;
        case 1: base = x0; break;
        case 2: base = x1; break;
        case 3: base = x2; break;
        default: base = x3; break;
    }
    const float4* p = reinterpret_cast<const float4*>(base + (size_t)(b * C_ + c) * HW_);
    float s = 0.f;
#pragma unroll
    for (int i = 0; i < 8; i++) {        // 8 * 32 lanes * 4 floats = 1024
        float4 v = p[lane + i * 32];
        s += (v.x + v.y) + (v.z + v.w);
    }
#pragma unroll
    for (int o = 16; o; o >>= 1) s += __shfl_xor_sync(0xffffffffu, s, o);
    if (lane == 0) g_feats[warp] = s * (1.0f / 1024.0f);
}

// ---------------- Kernel 2: gate MLP ----------------
// PDL secondary (waits on k_means data) AND PDL primary for k_apply:
// triggers at entry so apply's grid launches and prefetches concurrently.
__global__ void k_gate(const float* __restrict__ conv1_w,   // [32,1280]
                       const float* __restrict__ bn_gamma,
                       const float* __restrict__ bn_beta,
                       const float* __restrict__ bn_mean,
                       const float* __restrict__ bn_var,
                       const float* __restrict__ conv2_w,   // [1280,32]
                       const float* __restrict__ conv2_b) { // [1280]
    // Let dependent k_apply launch right away (it self-synchronizes).
    cudaTriggerProgrammaticLaunchCompletion();

    __shared__ float sf[FEAT_];
    __shared__ float sh[MID_];
    int b = blockIdx.x;
    int t = threadIdx.x;

    // Wait until k_means' writes to g_feats are visible.
    cudaGridDependencySynchronize();

    for (int i = t; i < FEAT_; i += 256) sf[i] = g_feats[b * FEAT_ + i];
    __syncthreads();

    int warp = t >> 5, lane = t & 31;
    // GEMM1: each warp computes 4 of the 32 mid channels
#pragma unroll
    for (int mi = 0; mi < 4; mi++) {
        int mid = warp * 4 + mi;
        const float* wr = conv1_w + mid * FEAT_;
        float s = 0.f;
#pragma unroll
        for (int j0 = 0; j0 < FEAT_; j0 += 32) s = fmaf(sf[j0 + lane], wr[j0 + lane], s);
#pragma unroll
        for (int o = 16; o; o >>= 1) s += __shfl_xor_sync(0xffffffffu, s, o);
        if (lane == 0) {
            float hv = (s - bn_mean[mid]) * (bn_gamma[mid] * rsqrtf(bn_var[mid] + 1e-5f))
                       + bn_beta[mid];
            sh[mid] = fmaxf(hv, 0.f);
        }
    }
    __syncthreads();

    // GEMM2: thread t owns channel c=t across all 5 slots (j = m*256 + t)
    float v[5];
#pragma unroll
    for (int m = 0; m < 5; m++) {
        int j = m * 256 + t;
        float s = conv2_b[j];
        const float* wr = conv2_w + j * MID_;
#pragma unroll
        for (int mid = 0; mid < MID_; mid++) s = fmaf(sh[mid], wr[mid], s);
        v[m] = s;
    }
    g_w1[b * C_ + t] = 1.0f / (1.0f + expf(-v[0]));
    float mx = fmaxf(fmaxf(v[1], v[2]), fmaxf(v[3], v[4]));
    float e1 = expf(v[1] - mx), e2 = expf(v[2] - mx);
    float e3 = expf(v[3] - mx), e4 = expf(v[4] - mx);
    float inv = 1.0f / (e1 + e2 + e3 + e4);
    int gb = b * K_ * C_ + t;
    g_w2[gb + 0 * C_] = e1 * inv;
    g_w2[gb + 1 * C_] = e2 * inv;
    g_w2[gb + 2 * C_] = e3 * inv;
    g_w2[gb + 3 * C_] = e4 * inv;
}

// ---------------- Kernel 3: apply gates (2 sweeps/thread, reversed, PDL) ----------------
// Launches while k_gate runs; issues its 10 gate-independent LDG.128 first,
// then waits on the grid dependency, then reads gates and computes.
__global__ void k_apply(const float* __restrict__ y,
                        const float* __restrict__ x0,
                        const float* __restrict__ x1,
                        const float* __restrict__ x2,
                        const float* __restrict__ x3,
                        float* __restrict__ out) {
    int blk = gridDim.x - 1 - blockIdx.x;            // reversed
    int t = threadIdx.x;
    int i0 = blk * 512 + t;                          // sweep 0 float4 index
    int i1 = i0 + 256;                               // sweep 1

    const float4* Y  = reinterpret_cast<const float4*>(y);
    const float4* X0 = reinterpret_cast<const float4*>(x0);
    const float4* X1 = reinterpret_cast<const float4*>(x1);
    const float4* X2 = reinterpret_cast<const float4*>(x2);
    const float4* X3 = reinterpret_cast<const float4*>(x3);

    // Gate-independent loads first: these overlap with k_gate's execution.
    float4 ya = Y[i0],  yb = Y[i1];
    float4 p0 = X0[i0], q0 = X0[i1];
    float4 p1 = X1[i0], q1 = X1[i1];
    float4 p2 = X2[i0], q2 = X2[i1];
    float4 p3 = X3[i0], q3 = X3[i1];

    // Now wait for k_gate's output to be visible.
    cudaGridDependencySynchronize();

    int bc0 = blk * 2;
    int bc1 = bc0 + 1;
    int b = bc0 >> 8;
    int c0 = bc0 & 255, c1 = bc1 & 255;
    float w1a = g_w1[bc0],               w1b = g_w1[bc1];
    int ga = b * K_ * C_ + c0,           gb = b * K_ * C_ + c1;
    float a0 = g_w2[ga + 0 * C_], b0 = g_w2[gb + 0 * C_];
    float a1 = g_w2[ga + 1 * C_], b1 = g_w2[gb + 1 * C_];
    float a2 = g_w2[ga + 2 * C_], b2 = g_w2[gb + 2 * C_];
    float a3 = g_w2[ga + 3 * C_], b3 = g_w2[gb + 3 * C_];

    float4 r;
    r.x = fmaf(ya.x, w1a, fmaf(a0, p0.x, fmaf(a1, p1.x, fmaf(a2, p2.x, a3 * p3.x))));
    r.y = fmaf(ya.y, w1a, fmaf(a0, p0.y, fmaf(a1, p1.y, fmaf(a2, p2.y, a3 * p3.y))));
    r.z = fmaf(ya.z, w1a, fmaf(a0, p0.z, fmaf(a1, p1.z, fmaf(a2, p2.z, a3 * p3.z))));
    r.w = fmaf(ya.w, w1a, fmaf(a0, p0.w, fmaf(a1, p1.w, fmaf(a2, p2.w, a3 * p3.w))));
    __stcs(reinterpret_cast<float4*>(out) + i0, r);

    float4 s;
    s.x = fmaf(yb.x, w1b, fmaf(b0, q0.x, fmaf(b1, q1.x, fmaf(b2, q2.x, b3 * q3.x))));
    s.y = fmaf(yb.y, w1b, fmaf(b0, q0.y, fmaf(b1, q1.y, fmaf(b2, q2.y, b3 * q3.y))));
    s.z = fmaf(yb.z, w1b, fmaf(b0, q0.z, fmaf(b1, q1.z, fmaf(b2, q2.z, b3 * q3.z))));
    s.w = fmaf(yb.w, w1b, fmaf(b0, q0.w, fmaf(b1, q1.w, fmaf(b2, q2.w, b3 * q3.w))));
    __stcs(reinterpret_cast<float4*>(out) + i1, s);
}

extern "C" void kernel_launch(void* const* d_in, const int* in_sizes, int n_in,
                              void* d_out, int out_size) {
    const float* y       = (const float*)d_in[0];
    const float* x0      = (const float*)d_in[1];
    const float* x1      = (const float*)d_in[2];
    const float* x2      = (const float*)d_in[3];
    const float* x3      = (const float*)d_in[4];
    const float* conv1_w = (const float*)d_in[5];
    const float* bn_g    = (const float*)d_in[6];
    const float* bn_b    = (const float*)d_in[7];
    const float* bn_m    = (const float*)d_in[8];
    const float* bn_v    = (const float*)d_in[9];
    const float* conv2_w = (const float*)d_in[10];
    const float* conv2_b = (const float*)d_in[11];
    float* out = (float*)d_out;

    // Kernel 1: plain launch
    k_means<<<5120, 256>>>(y, x0, x1, x2, x3);

    // PDL attribute: secondary launch may begin while predecessor drains.
    cudaLaunchAttribute attr[1];
    attr[0].id = cudaLaunchAttributeProgrammaticStreamSerialization;
    attr[0].val.programmaticStreamSerializationAllowed = 1;

    {   // Kernel 2: gate MLP, PDL-dependent on k_means
        cudaLaunchConfig_t cfg = {};
        cfg.gridDim = dim3(32, 1, 1);
        cfg.blockDim = dim3(256, 1, 1);
        cfg.dynamicSmemBytes = 0;
        cfg.stream = 0;
        cfg.attrs = attr;
        cfg.numAttrs = 1;
        cudaLaunchKernelEx(&cfg, k_gate, conv1_w, bn_g, bn_b, bn_m, bn_v,
                           conv2_w, conv2_b);
    }
    {   // Kernel 3: apply, PDL-dependent on k_gate (which triggers at entry)
        cudaLaunchConfig_t cfg = {};
        cfg.gridDim = dim3(4096, 1, 1);
        cfg.blockDim = dim3(256, 1, 1);
        cfg.dynamicSmemBytes = 0;
        cfg.stream = 0;
        cfg.attrs = attr;
        cfg.numAttrs = 1;
        cudaLaunchKernelEx(&cfg, k_apply, y, x0, x1, x2, x3, out);
    }
}